// round 3
// baseline (speedup 1.0000x reference)
#include <cuda_runtime.h>
#include <math.h>
#include <stdint.h>

// Problem constants
#define T_STEPS 1024
#define B_SZ    64
#define IN_SZ   512
#define HID_SZ  512
#define NCOL    2048               // 4 gates * HID
#define M_ROWS  (T_STEPS * B_SZ)   // 65536

// ---------------- f32x2 packed-FMA helpers (sm_103a FFMA2) ------------------
__device__ __forceinline__ unsigned long long fma2(unsigned long long a,
                                                   unsigned long long b,
                                                   unsigned long long c) {
    unsigned long long d;
    asm("fma.rn.f32x2 %0, %1, %2, %3;" : "=l"(d) : "l"(a), "l"(b), "l"(c));
    return d;
}
__device__ __forceinline__ unsigned long long pack2(float x, float y) {
    unsigned long long r;
    asm("mov.b64 %0, {%1, %2};" : "=l"(r) : "f"(x), "f"(y));
    return r;
}
__device__ __forceinline__ void unpack2(unsigned long long v, float& lo, float& hi) {
    asm("mov.b64 {%0, %1}, %2;" : "=f"(lo), "=f"(hi) : "l"(v));
}

// ---------------- device scratch (static; no runtime allocation) ------------
__device__ float g_WX[IN_SZ * NCOL];                 // [k][g*512+n]  4 MB
__device__ float g_WH[HID_SZ * NCOL];                // [k][g*512+n]  4 MB
__device__ float g_XG[(size_t)M_ROWS * NCOL];        // 512 MB: X@Wx + bias
__device__ float g_HT[2][HID_SZ * B_SZ];             // transposed H, double buffer
__device__ unsigned int g_bar_count = 0;
__device__ volatile unsigned int g_bar_sense = 0;

// ---------------- kernel 1: threshold-mask + transpose weights --------------
__global__ void mask_weights(const float* __restrict__ Wx,
                             const float* __restrict__ Wh,
                             const float* __restrict__ thr) {
    int idx = blockIdx.x * blockDim.x + threadIdx.x;   // over 4*512*512
    if (idx >= 4 * HID_SZ * IN_SZ) return;
    int g = idx / (HID_SZ * IN_SZ);
    int rem = idx % (HID_SZ * IN_SZ);
    int n = rem / IN_SZ;     // output neuron
    int i = rem % IN_SZ;     // contraction index
    float wx = Wx[idx];
    float tx = thr[n * 8 + g];
    g_WX[(size_t)i * NCOL + g * HID_SZ + n] = (fabsf(wx) >= tx) ? wx : 0.0f;
    float wh = Wh[idx];
    float th = thr[n * 8 + 4 + g];
    g_WH[(size_t)i * NCOL + g * HID_SZ + n] = (fabsf(wh) >= th) ? wh : 0.0f;
}

// ---------------- kernel 2: XG = X @ WX + bias  (65536 x 2048 x 512) --------
// 128x128x16 tile, 256 threads, 8x8 per thread, FFMA2 inner product
#define BM 128
#define BN 128
#define BK 16
__global__ void __launch_bounds__(256, 2)
gemm_xw(const float* __restrict__ X, const float* __restrict__ bias) {
    __shared__ float As[BK][BM];   // A stored transposed: As[k][m]
    __shared__ float Bs[BK][BN];
    const int tid = threadIdx.x;
    const int bm = blockIdx.y * BM;
    const int bn = blockIdx.x * BN;
    const int tx = tid % 16;
    const int ty = tid / 16;

    unsigned long long acc[8][4];          // 8 rows x 4 col-pairs (f32x2)
#pragma unroll
    for (int i = 0; i < 8; i++)
#pragma unroll
        for (int j = 0; j < 4; j++) acc[i][j] = 0ull;

    const int a_row  = tid / 4;          // 0..63
    const int a_col4 = (tid % 4) * 4;    // 0,4,8,12
    const int b_row  = tid / 32;         // 0..7
    const int b_col  = (tid % 32) * 4;

    for (int k0 = 0; k0 < IN_SZ; k0 += BK) {
#pragma unroll
        for (int r = 0; r < 2; r++) {
            int m = a_row + r * 64;
            float4 v = *(const float4*)&X[(size_t)(bm + m) * IN_SZ + k0 + a_col4];
            As[a_col4 + 0][m] = v.x;
            As[a_col4 + 1][m] = v.y;
            As[a_col4 + 2][m] = v.z;
            As[a_col4 + 3][m] = v.w;
        }
#pragma unroll
        for (int r = 0; r < 2; r++) {
            int kk = b_row + r * 8;
            *(float4*)&Bs[kk][b_col] =
                *(const float4*)&g_WX[(size_t)(k0 + kk) * NCOL + bn + b_col];
        }
        __syncthreads();
#pragma unroll
        for (int k = 0; k < BK; k++) {
            float ra[8];
            *(float4*)&ra[0] = *(const float4*)&As[k][ty * 8];
            *(float4*)&ra[4] = *(const float4*)&As[k][ty * 8 + 4];
            ulonglong2 b01 = *(const ulonglong2*)&Bs[k][tx * 8];
            ulonglong2 b23 = *(const ulonglong2*)&Bs[k][tx * 8 + 4];
#pragma unroll
            for (int i = 0; i < 8; i++) {
                unsigned long long ai = pack2(ra[i], ra[i]);
                acc[i][0] = fma2(ai, b01.x, acc[i][0]);
                acc[i][1] = fma2(ai, b01.y, acc[i][1]);
                acc[i][2] = fma2(ai, b23.x, acc[i][2]);
                acc[i][3] = fma2(ai, b23.y, acc[i][3]);
            }
        }
        __syncthreads();
    }
    // epilogue: unpack, += bias, store
#pragma unroll
    for (int i = 0; i < 8; i++) {
        size_t m = (size_t)(bm + ty * 8 + i);
#pragma unroll
        for (int j = 0; j < 2; j++) {
            int n = bn + tx * 8 + j * 4;
            float4 v;
            unpack2(acc[i][j * 2 + 0], v.x, v.y);
            unpack2(acc[i][j * 2 + 1], v.z, v.w);
            v.x += bias[n + 0];
            v.y += bias[n + 1];
            v.z += bias[n + 2];
            v.w += bias[n + 3];
            *(float4*)&g_XG[m * NCOL + n] = v;
        }
    }
}

// ---------------- grid barrier (sense-reversing, 128 co-resident CTAs) ------
__device__ __forceinline__ void grid_barrier(unsigned int s) {
    __threadfence();            // publish this thread's writes
    __syncthreads();
    if (threadIdx.x == 0) {
        unsigned int v = atomicAdd(&g_bar_count, 1u);
        if (v == gridDim.x - 1) {
            g_bar_count = 0u;
            __threadfence();
            g_bar_sense = s;
        } else {
            while (g_bar_sense != s) { }
            __threadfence();
        }
    }
    __syncthreads();
}

// ---------------- cp.async helpers ------------------------------------------
__device__ __forceinline__ void cpasync16(uint32_t smem_dst, const void* gsrc) {
    asm volatile("cp.async.cg.shared.global [%0], [%1], 16;"
                 :: "r"(smem_dst), "l"(gsrc));
}
__device__ __forceinline__ void cpasync_commit() {
    asm volatile("cp.async.commit_group;");
}
__device__ __forceinline__ void cpasync_wait0() {
    asm volatile("cp.async.wait_group 0;");
}

// ---------------- kernel 3: persistent recurrent LSTM -----------------------
// 128 CTAs x 256 threads. CTA c owns h-columns [c*4, c*4+4) for all 4 gates.
// Wh slice in SMEM as duplicated (w,w) pairs for FFMA2. H chunks staged via
// cp.async double-buffer, overlapped with compute. C stays in registers.
__global__ void __launch_bounds__(256, 1)
lstm_recurrent(const float* __restrict__ h0, const float* __restrict__ c0,
               float* __restrict__ out) {
    extern __shared__ char smem_raw[];
    unsigned long long* Ws2 = (unsigned long long*)smem_raw;     // 512*16*8B = 64KB
    float* Hs0 = (float*)(smem_raw + 65536);                     // 128x64 f32 = 32KB
    float* Hs1 = (float*)(smem_raw + 65536 + 32768);             // 32KB
    float* Gs  = (float*)(smem_raw + 65536 + 65536);             // 64x16 f32 = 4KB
    float* HsBuf[2] = {Hs0, Hs1};

    const int tid = threadIdx.x;
    const int cta = blockIdx.x;          // 0..127
    const int hc0 = cta * 4;

    // Load this CTA's Wh slice as (w,w) f32x2 pairs.
    // col = g*4+j  <->  WH col n = g*512 + hc0 + j
    for (int idx = tid; idx < 512 * 16; idx += 256) {
        int k = idx / 16;
        int col = idx % 16;
        int g = col >> 2, j = col & 3;
        float w = g_WH[(size_t)k * NCOL + g * HID_SZ + hc0 + j];
        Ws2[idx] = pack2(w, w);
    }

    // GEMM mapping: thread computes rows [rgrp*4, rgrp*4+4) x 1 gate-column
    const int col  = tid % 16;
    const int rgrp = tid / 16;
    // pointwise mapping: thread owns (batch pb, local hidden col phc)
    const int pb  = tid / 4;
    const int phc = tid % 4;

    float creg = c0[pb * HID_SZ + hc0 + phc];

    // smem addresses for cp.async destinations
    const uint32_t hs_addr[2] = {
        (uint32_t)__cvta_generic_to_shared(Hs0),
        (uint32_t)__cvta_generic_to_shared(Hs1)
    };

    // init transposed H buffer 0 (this CTA's 4 columns, all batches)
    for (int i = tid; i < 4 * B_SZ; i += 256) {
        int j = i / B_SZ, b = i % B_SZ;
        g_HT[0][(hc0 + j) * B_SZ + b] = h0[b * HID_SZ + hc0 + j];
    }
    grid_barrier(1);

    for (int t = 0; t < T_STEPS; t++) {
        const int cur = t & 1;
        const float* HTsrc = g_HT[cur];

        // prefetch XG contributions for the pointwise stage
        const float* xg = &g_XG[(size_t)(t * B_SZ + pb) * NCOL + hc0 + phc];
        float xgi = __ldg(xg + 0);
        float xgf = __ldg(xg + 512);
        float xgo = __ldg(xg + 1024);
        float xgc = __ldg(xg + 1536);

        // stage chunk 0 into buffer 0
        {
            const float* src = &HTsrc[0];
#pragma unroll
            for (int r = 0; r < 8; r++)
                cpasync16(hs_addr[0] + (r * 256 + tid) * 16,
                          src + (r * 256 + tid) * 4);
            cpasync_commit();
        }

        unsigned long long acc01 = 0ull, acc23 = 0ull;

#pragma unroll
        for (int kc = 0; kc < 4; kc++) {
            cpasync_wait0();          // chunk kc fully arrived (this thread)
            __syncthreads();          // all threads arrived; prev compute done
            if (kc < 3) {             // stage next chunk into the other buffer
                const float* src = &HTsrc[(kc + 1) * 8192];
#pragma unroll
                for (int r = 0; r < 8; r++)
                    cpasync16(hs_addr[(kc + 1) & 1] + (r * 256 + tid) * 16,
                              src + (r * 256 + tid) * 4);
                cpasync_commit();
            }
            const float* Hc = HsBuf[kc & 1];
            const unsigned long long* Wp = &Ws2[(kc * 128) * 16 + col];
#pragma unroll 4
            for (int k = 0; k < 128; k++) {
                unsigned long long w2 = Wp[k * 16];
                ulonglong2 h2 = *(const ulonglong2*)&Hc[k * 64 + rgrp * 4];
                acc01 = fma2(h2.x, w2, acc01);
                acc23 = fma2(h2.y, w2, acc23);
            }
        }

        __syncthreads();
        {
            float a0, a1, a2, a3;
            unpack2(acc01, a0, a1);
            unpack2(acc23, a2, a3);
            Gs[(rgrp * 4 + 0) * 16 + col] = a0;
            Gs[(rgrp * 4 + 1) * 16 + col] = a1;
            Gs[(rgrp * 4 + 2) * 16 + col] = a2;
            Gs[(rgrp * 4 + 3) * 16 + col] = a3;
        }
        __syncthreads();

        float gi = Gs[pb * 16 + 0  + phc] + xgi;
        float gf = Gs[pb * 16 + 4  + phc] + xgf;
        float go = Gs[pb * 16 + 8  + phc] + xgo;
        float gc = Gs[pb * 16 + 12 + phc] + xgc;

        float I = 1.0f / (1.0f + expf(-gi));
        float F = 1.0f / (1.0f + expf(-gf));
        float O = 1.0f / (1.0f + expf(-go));
        float Ct = tanhf(gc);
        creg = F * creg + I * Ct;
        float h = O * tanhf(creg);

        g_HT[cur ^ 1][(hc0 + phc) * B_SZ + pb] = h;
        out[(size_t)(t * B_SZ + pb) * HID_SZ + hc0 + phc] = h;

        grid_barrier((unsigned)(t + 2));
    }
}

// ---------------- launcher ---------------------------------------------------
extern "C" void kernel_launch(void* const* d_in, const int* in_sizes, int n_in,
                              void* d_out, int out_size) {
    const float* X    = (const float*)d_in[0];   // (T,B,IN)
    const float* Wx   = (const float*)d_in[1];   // (4,HID,IN)
    const float* Wh   = (const float*)d_in[2];   // (4,HID,HID)
    const float* bias = (const float*)d_in[3];   // (4,HID)
    const float* thr  = (const float*)d_in[4];   // (HID,8)
    const float* h0   = (const float*)d_in[5];   // (B,HID)
    const float* c0   = (const float*)d_in[6];   // (B,HID)
    float* out = (float*)d_out;                  // (T,B,HID)

    // 1) masked + transposed weights
    mask_weights<<<(4 * HID_SZ * IN_SZ + 255) / 256, 256>>>(Wx, Wh, thr);

    // 2) input projection for all timesteps (one big GEMM, FFMA2)
    dim3 g2(NCOL / BN, M_ROWS / BM);   // (16, 512)
    gemm_xw<<<g2, 256>>>(X, bias);

    // 3) persistent recurrent kernel
    const int smem_bytes = 65536 + 65536 + 4096;  // Ws2 + 2x Hs + Gs = 135168
    cudaFuncSetAttribute(lstm_recurrent,
                         cudaFuncAttributeMaxDynamicSharedMemorySize, smem_bytes);
    lstm_recurrent<<<128, 256, smem_bytes>>>(h0, c0, out);
}

// round 4
// speedup vs baseline: 1.2809x; 1.2809x over previous
#include <cuda_runtime.h>
#include <math.h>
#include <stdint.h>

// Problem constants
#define T_STEPS 1024
#define B_SZ    64
#define IN_SZ   512
#define HID_SZ  512
#define NCOL    2048               // 4 gates * HID
#define M_ROWS  (T_STEPS * B_SZ)   // 65536

// ---------------- f32x2 packed helpers (sm_103a FFMA2) ----------------------
__device__ __forceinline__ unsigned long long fma2(unsigned long long a,
                                                   unsigned long long b,
                                                   unsigned long long c) {
    unsigned long long d;
    asm("fma.rn.f32x2 %0, %1, %2, %3;" : "=l"(d) : "l"(a), "l"(b), "l"(c));
    return d;
}
__device__ __forceinline__ unsigned long long add2(unsigned long long a,
                                                   unsigned long long b) {
    unsigned long long d;
    asm("add.rn.f32x2 %0, %1, %2;" : "=l"(d) : "l"(a), "l"(b));
    return d;
}
__device__ __forceinline__ unsigned long long pack2(float x, float y) {
    unsigned long long r;
    asm("mov.b64 %0, {%1, %2};" : "=l"(r) : "f"(x), "f"(y));
    return r;
}
__device__ __forceinline__ void unpack2(unsigned long long v, float& lo, float& hi) {
    asm("mov.b64 {%0, %1}, %2;" : "=f"(lo), "=f"(hi) : "l"(v));
}

// ---------------- device scratch (static; no runtime allocation) ------------
__device__ float g_WX[IN_SZ * NCOL];                 // [k][g*512+n]  4 MB
__device__ float g_WH[HID_SZ * NCOL];                // [k][g*512+n]  4 MB
__device__ float g_XG[(size_t)M_ROWS * NCOL];        // 512 MB: X@Wx + bias
__device__ float g_HT[2][HID_SZ * B_SZ];             // H transposed [hid][b], dbl buf
__device__ unsigned int g_bar_count = 0;
__device__ volatile unsigned int g_bar_sense = 0;

// ---------------- kernel 1: threshold-mask + transpose weights --------------
__global__ void mask_weights(const float* __restrict__ Wx,
                             const float* __restrict__ Wh,
                             const float* __restrict__ thr) {
    int idx = blockIdx.x * blockDim.x + threadIdx.x;   // over 4*512*512
    if (idx >= 4 * HID_SZ * IN_SZ) return;
    int g = idx / (HID_SZ * IN_SZ);
    int rem = idx % (HID_SZ * IN_SZ);
    int n = rem / IN_SZ;     // output neuron
    int i = rem % IN_SZ;     // contraction index
    float wx = Wx[idx];
    float tx = thr[n * 8 + g];
    g_WX[(size_t)i * NCOL + g * HID_SZ + n] = (fabsf(wx) >= tx) ? wx : 0.0f;
    float wh = Wh[idx];
    float th = thr[n * 8 + 4 + g];
    g_WH[(size_t)i * NCOL + g * HID_SZ + n] = (fabsf(wh) >= th) ? wh : 0.0f;
}

// ---------------- kernel 2: XG = X @ WX + bias  (65536 x 2048 x 512) --------
// 128x128x16 tile, 256 threads, 8x8/thread, FFMA2 with pre-duplicated A pairs
#define BM 128
#define BN 128
#define BK 16
__global__ void __launch_bounds__(256, 2)
gemm_xw(const float* __restrict__ X, const float* __restrict__ bias) {
    __shared__ unsigned long long As2[BK * BM];   // (a,a) pairs, 16 KB
    __shared__ float Bs[BK][BN];                  // 8 KB
    const int tid = threadIdx.x;
    const int bm = blockIdx.y * BM;
    const int bn = blockIdx.x * BN;
    const int tx = tid % 16;
    const int ty = tid / 16;

    unsigned long long acc[8][4];          // 8 rows x 4 col-pairs (f32x2)
#pragma unroll
    for (int i = 0; i < 8; i++)
#pragma unroll
        for (int j = 0; j < 4; j++) acc[i][j] = 0ull;

    const int a_row  = tid / 4;          // 0..63
    const int a_col4 = (tid % 4) * 4;    // 0,4,8,12
    const int b_row  = tid / 32;         // 0..7
    const int b_col  = (tid % 32) * 4;

    for (int k0 = 0; k0 < IN_SZ; k0 += BK) {
#pragma unroll
        for (int r = 0; r < 2; r++) {
            int m = a_row + r * 64;
            float4 v = *(const float4*)&X[(size_t)(bm + m) * IN_SZ + k0 + a_col4];
            As2[(a_col4 + 0) * BM + m] = pack2(v.x, v.x);
            As2[(a_col4 + 1) * BM + m] = pack2(v.y, v.y);
            As2[(a_col4 + 2) * BM + m] = pack2(v.z, v.z);
            As2[(a_col4 + 3) * BM + m] = pack2(v.w, v.w);
        }
#pragma unroll
        for (int r = 0; r < 2; r++) {
            int kk = b_row + r * 8;
            *(float4*)&Bs[kk][b_col] =
                *(const float4*)&g_WX[(size_t)(k0 + kk) * NCOL + bn + b_col];
        }
        __syncthreads();
#pragma unroll
        for (int k = 0; k < BK; k++) {
            unsigned long long ra[8];
            *(ulonglong2*)&ra[0] = *(const ulonglong2*)&As2[k * BM + ty * 8];
            *(ulonglong2*)&ra[2] = *(const ulonglong2*)&As2[k * BM + ty * 8 + 2];
            *(ulonglong2*)&ra[4] = *(const ulonglong2*)&As2[k * BM + ty * 8 + 4];
            *(ulonglong2*)&ra[6] = *(const ulonglong2*)&As2[k * BM + ty * 8 + 6];
            ulonglong2 b01 = *(const ulonglong2*)&Bs[k][tx * 8];
            ulonglong2 b23 = *(const ulonglong2*)&Bs[k][tx * 8 + 4];
#pragma unroll
            for (int i = 0; i < 8; i++) {
                acc[i][0] = fma2(ra[i], b01.x, acc[i][0]);
                acc[i][1] = fma2(ra[i], b01.y, acc[i][1]);
                acc[i][2] = fma2(ra[i], b23.x, acc[i][2]);
                acc[i][3] = fma2(ra[i], b23.y, acc[i][3]);
            }
        }
        __syncthreads();
    }
    // epilogue: unpack, += bias, store
#pragma unroll
    for (int i = 0; i < 8; i++) {
        size_t m = (size_t)(bm + ty * 8 + i);
#pragma unroll
        for (int j = 0; j < 2; j++) {
            int n = bn + tx * 8 + j * 4;
            float4 v;
            unpack2(acc[i][j * 2 + 0], v.x, v.y);
            unpack2(acc[i][j * 2 + 1], v.z, v.w);
            v.x += bias[n + 0];
            v.y += bias[n + 1];
            v.z += bias[n + 2];
            v.w += bias[n + 3];
            *(float4*)&g_XG[m * NCOL + n] = v;
        }
    }
}

// ---------------- grid barrier (sense-reversing, 128 co-resident CTAs) ------
__device__ __forceinline__ void grid_barrier(unsigned int s) {
    __threadfence();            // publish this thread's writes
    __syncthreads();
    if (threadIdx.x == 0) {
        unsigned int v = atomicAdd(&g_bar_count, 1u);
        if (v == gridDim.x - 1) {
            g_bar_count = 0u;
            __threadfence();
            g_bar_sense = s;
        } else {
            while (g_bar_sense != s) { }
            __threadfence();
        }
    }
    __syncthreads();
}

// ---------------- cp.async helpers ------------------------------------------
__device__ __forceinline__ void cpasync16(uint32_t smem_dst, const void* gsrc) {
    asm volatile("cp.async.cg.shared.global [%0], [%1], 16;"
                 :: "r"(smem_dst), "l"(gsrc));
}
__device__ __forceinline__ void cpasync_commit() {
    asm volatile("cp.async.commit_group;");
}

// ---------------- kernel 3: persistent recurrent LSTM -----------------------
// 128 CTAs = 64 colgroups x 2 batch-halves. CTA owns 32 gate-cols (8 hidden
// units x 4 gates) x 32 batches. W slice (512x32, 64KB) SMEM-resident for all
// steps. Warp = 32 batches (lane=batch) x 32 cols; 8 warps split k 8 ways,
// partials reduced via SMEM with add.f32x2. H staged per step via cp.async
// (2-chunk double buffer). W is warp-uniform -> broadcast LDS (1 wf each);
// h load is coalesced (1 wf). C stays in registers.
__global__ void __launch_bounds__(256, 1)
lstm_recurrent(const float* __restrict__ h0, const float* __restrict__ c0,
               float* __restrict__ out) {
    extern __shared__ char smem_raw[];
    float* Ws = (float*)smem_raw;                                   // [512][32] 64KB
    float* Hs = (float*)(smem_raw + 65536);                         // 2x[256][32] 64KB
    unsigned long long* Rs = (unsigned long long*)(smem_raw + 131072); // [16][8][32] 32KB
    float* Gs = (float*)(smem_raw + 131072 + 32768);                // [32][33] 4.2KB

    const int tid  = threadIdx.x;
    const int warp = tid >> 5;
    const int lane = tid & 31;
    const int cg   = blockIdx.x >> 1;     // 0..63 column group
    const int bh   = blockIdx.x & 1;      // batch half
    const int hu0  = cg * 8;              // first hidden unit

    // Load W slice: Ws[k][c] = WH[k][(c>>3)*512 + hu0 + (c&7)], c = g*8+j
    for (int idx = tid; idx < 512 * 32; idx += 256) {
        int k = idx >> 5, c = idx & 31;
        Ws[idx] = g_WH[(size_t)k * NCOL + (c >> 3) * HID_SZ + hu0 + (c & 7)];
    }

    // pointwise mapping: thread -> (local batch pb, hidden unit pj)
    const int pb  = tid >> 3;             // 0..31
    const int pj  = tid & 7;              // 0..7
    const int b_g = bh * 32 + pb;         // global batch

    float creg = c0[b_g * HID_SZ + hu0 + pj];

    const uint32_t hs_base = (uint32_t)__cvta_generic_to_shared(Hs);

    // init g_HT[0]: CTA covers k in [cg*8, cg*8+8) x its 32 batches
    {
        int k = cg * 8 + (tid >> 5);
        int b = bh * 32 + (tid & 31);
        g_HT[0][k * B_SZ + b] = h0[b * HID_SZ + k];
    }
    grid_barrier(1);

    for (int t = 0; t < T_STEPS; t++) {
        const int cur = t & 1;
        const float* HT = g_HT[cur];

        // prefetch XG for pointwise (overlaps with staging+GEMM)
        const float* xg = &g_XG[(size_t)(t * B_SZ + b_g) * NCOL + hu0 + pj];
        float xgi = __ldg(xg + 0);
        float xgf = __ldg(xg + 512);
        float xgo = __ldg(xg + 1024);
        float xgc = __ldg(xg + 1536);

        // stage both H chunks (k 0..255, 256..511) for this batch half
#pragma unroll
        for (int c = 0; c < 2; c++) {
#pragma unroll
            for (int r = 0; r < 8; r++) {
                int s  = r * 256 + tid;        // 0..2047
                int kl = s >> 3;               // local k row 0..255
                int b4 = (s & 7) * 4;          // 4-float segment
                cpasync16(hs_base + (uint32_t)(c * 8192 + kl * 32 + b4) * 4,
                          HT + (c * 256 + kl) * B_SZ + bh * 32 + b4);
            }
            cpasync_commit();
        }

        unsigned long long acc[16];
#pragma unroll
        for (int i = 0; i < 16; i++) acc[i] = 0ull;

        // two chunks; warp handles k-seg [warp*32, warp*32+32) within each
#pragma unroll
        for (int c = 0; c < 2; c++) {
            if (c == 0) asm volatile("cp.async.wait_group 1;");
            else        asm volatile("cp.async.wait_group 0;");
            __syncthreads();
            const float* Hc = Hs + c * 8192 + (warp * 32) * 32;
            const unsigned long long* Wp =
                (const unsigned long long*)(Ws + (c * 256 + warp * 32) * 32);
#pragma unroll 4
            for (int k = 0; k < 32; k++) {
                float h = Hc[k * 32 + lane];
                unsigned long long h2 = pack2(h, h);
                const ulonglong2* wrow = (const ulonglong2*)(Wp + k * 16);
#pragma unroll
                for (int i = 0; i < 8; i++) {
                    ulonglong2 w = wrow[i];
                    acc[2 * i + 0] = fma2(h2, w.x, acc[2 * i + 0]);
                    acc[2 * i + 1] = fma2(h2, w.y, acc[2 * i + 1]);
                }
            }
        }

        // write k-partials: Rs[c2][warp][lane]
#pragma unroll
        for (int c2 = 0; c2 < 16; c2++)
            Rs[(c2 * 8 + warp) * 32 + lane] = acc[c2];
        __syncthreads();

        // reduce 8 partials -> Gs[b][c]; each thread handles 2 (b,c2) pairs
#pragma unroll
        for (int pp = 0; pp < 2; pp++) {
            int p  = tid + pp * 256;
            int c2 = p >> 5, b = p & 31;
            const unsigned long long* rp = &Rs[(c2 * 8) * 32 + b];
            unsigned long long s = rp[0];
#pragma unroll
            for (int q = 1; q < 8; q++) s = add2(s, rp[q * 32]);
            float lo, hi;
            unpack2(s, lo, hi);
            Gs[b * 33 + 2 * c2 + 0] = lo;
            Gs[b * 33 + 2 * c2 + 1] = hi;
        }
        __syncthreads();

        // pointwise LSTM cell
        float gi = Gs[pb * 33 + 0  + pj] + xgi;
        float gf = Gs[pb * 33 + 8  + pj] + xgf;
        float go = Gs[pb * 33 + 16 + pj] + xgo;
        float gc = Gs[pb * 33 + 24 + pj] + xgc;

        float I = 1.0f / (1.0f + expf(-gi));
        float F = 1.0f / (1.0f + expf(-gf));
        float O = 1.0f / (1.0f + expf(-go));
        float Ct = tanhf(gc);
        creg = F * creg + I * Ct;
        float h = O * tanhf(creg);

        g_HT[cur ^ 1][(hu0 + pj) * B_SZ + b_g] = h;
        out[(size_t)(t * B_SZ + b_g) * HID_SZ + hu0 + pj] = h;

        grid_barrier((unsigned)(t + 2));
    }
}

// ---------------- launcher ---------------------------------------------------
extern "C" void kernel_launch(void* const* d_in, const int* in_sizes, int n_in,
                              void* d_out, int out_size) {
    const float* X    = (const float*)d_in[0];   // (T,B,IN)
    const float* Wx   = (const float*)d_in[1];   // (4,HID,IN)
    const float* Wh   = (const float*)d_in[2];   // (4,HID,HID)
    const float* bias = (const float*)d_in[3];   // (4,HID)
    const float* thr  = (const float*)d_in[4];   // (HID,8)
    const float* h0   = (const float*)d_in[5];   // (B,HID)
    const float* c0   = (const float*)d_in[6];   // (B,HID)
    float* out = (float*)d_out;                  // (T,B,HID)

    // 1) masked + transposed weights
    mask_weights<<<(4 * HID_SZ * IN_SZ + 255) / 256, 256>>>(Wx, Wh, thr);

    // 2) input projection for all timesteps (one big GEMM, FFMA2)
    dim3 g2(NCOL / BN, M_ROWS / BM);   // (16, 512)
    gemm_xw<<<g2, 256>>>(X, bias);

    // 3) persistent recurrent kernel
    const int smem_bytes = 65536 + 65536 + 32768 + 32 * 33 * 4;  // 168448
    cudaFuncSetAttribute(lstm_recurrent,
                         cudaFuncAttributeMaxDynamicSharedMemorySize, smem_bytes);
    lstm_recurrent<<<128, 256, smem_bytes>>>(h0, c0, out);
}

// round 6
// speedup vs baseline: 1.7696x; 1.3815x over previous
#include <cuda_runtime.h>
#include <cuda_bf16.h>
#include <math.h>
#include <stdint.h>

// Problem constants
#define T_STEPS 1024
#define B_SZ    64
#define IN_SZ   512
#define HID_SZ  512
#define NCOL    2048               // 4 gates * HID
#define M_ROWS  (T_STEPS * B_SZ)   // 65536

// ---------------- device scratch (static; no runtime allocation) ------------
__device__ __nv_bfloat16 g_XH[(size_t)M_ROWS * IN_SZ];   // X hi split, 64 MB
__device__ __nv_bfloat16 g_XL[(size_t)M_ROWS * IN_SZ];   // X lo split, 64 MB
__device__ __nv_bfloat16 g_WXH[NCOL * IN_SZ];            // Wx hi [col][k]
__device__ __nv_bfloat16 g_WXL[NCOL * IN_SZ];            // Wx lo [col][k]
__device__ __nv_bfloat16 g_WHH[NCOL * HID_SZ];           // Wh hi [col][k]
__device__ __nv_bfloat16 g_WHL[NCOL * HID_SZ];           // Wh lo [col][k]
__device__ float g_XG[(size_t)M_ROWS * NCOL];            // 512 MB: X@Wx + bias
__device__ __nv_bfloat16 g_HBH[2][B_SZ * HID_SZ];        // H hi [b][k], dbl buf
__device__ __nv_bfloat16 g_HBL[2][B_SZ * HID_SZ];        // H lo [b][k], dbl buf
__device__ unsigned int g_bar_count = 0;
__device__ volatile unsigned int g_bar_sense = 0;

// ---------------- helpers -----------------------------------------------------
__device__ __forceinline__ void split_bf16(float x, __nv_bfloat16& hi,
                                           __nv_bfloat16& lo) {
    hi = __float2bfloat16_rn(x);
    lo = __float2bfloat16_rn(x - __bfloat162float(hi));
}
__device__ __forceinline__ uint32_t smem_u32(const void* p) {
    uint32_t a;
    asm("{ .reg .u64 t; cvta.to.shared.u64 t, %1; cvt.u32.u64 %0, t; }"
        : "=r"(a) : "l"(p));
    return a;
}
__device__ __forceinline__ void cpasync16(uint32_t smem_dst, const void* gsrc) {
    asm volatile("cp.async.cg.shared.global [%0], [%1], 16;"
                 :: "r"(smem_dst), "l"(gsrc));
}
__device__ __forceinline__ void cpasync_commit() {
    asm volatile("cp.async.commit_group;");
}
__device__ __forceinline__ void ldsm4(uint32_t* r, uint32_t addr) {
    asm volatile("ldmatrix.sync.aligned.m8n8.x4.shared.b16 {%0,%1,%2,%3}, [%4];"
                 : "=r"(r[0]), "=r"(r[1]), "=r"(r[2]), "=r"(r[3]) : "r"(addr));
}
__device__ __forceinline__ void mma16816(float* c, const uint32_t* a,
                                         const uint32_t* b) {
    asm volatile(
        "mma.sync.aligned.m16n8k16.row.col.f32.bf16.bf16.f32 "
        "{%0,%1,%2,%3}, {%4,%5,%6,%7}, {%8,%9}, {%0,%1,%2,%3};"
        : "+f"(c[0]), "+f"(c[1]), "+f"(c[2]), "+f"(c[3])
        : "r"(a[0]), "r"(a[1]), "r"(a[2]), "r"(a[3]), "r"(b[0]), "r"(b[1]));
}

// ---------------- kernel 1: threshold-mask + bf16 hi/lo weight splits --------
__global__ void mask_weights(const float* __restrict__ Wx,
                             const float* __restrict__ Wh,
                             const float* __restrict__ thr) {
    int idx = blockIdx.x * blockDim.x + threadIdx.x;   // over 4*512*512
    if (idx >= 4 * HID_SZ * IN_SZ) return;
    int g = idx / (HID_SZ * IN_SZ);
    int rem = idx % (HID_SZ * IN_SZ);
    int n = rem / IN_SZ;
    int i = rem % IN_SZ;
    size_t o = (size_t)(g * HID_SZ + n) * IN_SZ + i;

    float wx = Wx[idx];
    float vx = (fabsf(wx) >= thr[n * 8 + g]) ? wx : 0.0f;
    split_bf16(vx, g_WXH[o], g_WXL[o]);

    float wh = Wh[idx];
    float vh = (fabsf(wh) >= thr[n * 8 + 4 + g]) ? wh : 0.0f;
    split_bf16(vh, g_WHH[o], g_WHL[o]);
}

// ---------------- kernel 2: split X into bf16 hi/lo ---------------------------
__global__ void split_x(const float* __restrict__ X) {
    size_t i = ((size_t)blockIdx.x * blockDim.x + threadIdx.x) * 4;
    if (i >= (size_t)M_ROWS * IN_SZ) return;
    float4 x = *(const float4*)&X[i];
    __nv_bfloat16 h[4], l[4];
    split_bf16(x.x, h[0], l[0]);
    split_bf16(x.y, h[1], l[1]);
    split_bf16(x.z, h[2], l[2]);
    split_bf16(x.w, h[3], l[3]);
    *(__nv_bfloat162*)&g_XH[i]     = __nv_bfloat162(h[0], h[1]);
    *(__nv_bfloat162*)&g_XH[i + 2] = __nv_bfloat162(h[2], h[3]);
    *(__nv_bfloat162*)&g_XL[i]     = __nv_bfloat162(l[0], l[1]);
    *(__nv_bfloat162*)&g_XL[i + 2] = __nv_bfloat162(l[2], l[3]);
}

// ---------------- kernel 3: XG = X @ WX^T + bias via mma.sync bf16x2 ----------
// 128x128 tile, K chunks of 64, triple-buffered cp.async, 8 warps (2m x 4n),
// warp tile 64x32. 3 products: Xh*Wh + Xh*Wl + Xl*Wh (fp32 accum).
#define G_SAS  72                       // halves per staged row (64 + 8 pad)
#define G_MATB (128 * G_SAS * 2)        // 18432 B per matrix
#define G_BUFB (4 * G_MATB)             // 73728 B per buffer (Ah,Al,Bh,Bl)

__device__ __forceinline__ void gemm_stage(uint32_t sb, int kc, int bm, int bn,
                                           int tid) {
    uint32_t buf = sb + (uint32_t)(kc % 3) * G_BUFB;
#pragma unroll
    for (int j = 0; j < 16; j++) {
        int lin = j * 256 + tid;            // 0..4095
        int mat = lin >> 10;                // 0:Ah 1:Al 2:Bh 3:Bl
        int within = lin & 1023;
        int row = within >> 3;
        int seg = within & 7;
        uint32_t dst = buf + (uint32_t)mat * G_MATB + row * (G_SAS * 2) + seg * 16;
        size_t koff = (size_t)kc * 64 + seg * 8;
        const __nv_bfloat16* src;
        if (mat == 0)      src = &g_XH[(size_t)(bm + row) * IN_SZ + koff];
        else if (mat == 1) src = &g_XL[(size_t)(bm + row) * IN_SZ + koff];
        else if (mat == 2) src = &g_WXH[(size_t)(bn + row) * IN_SZ + koff];
        else               src = &g_WXL[(size_t)(bn + row) * IN_SZ + koff];
        cpasync16(dst, src);
    }
    cpasync_commit();
}

__global__ void __launch_bounds__(256, 1)
gemm_mma(const float* __restrict__ bias) {
    extern __shared__ char sm[];
    const uint32_t sb = smem_u32(sm);
    const int tid = threadIdx.x;
    const int wid = tid >> 5;
    const int lane = tid & 31;
    const int bm = blockIdx.y * 128;
    const int bn = blockIdx.x * 128;
    const int wm = wid & 1;       // m-offset wm*64
    const int wn = wid >> 1;      // n-offset wn*32

    float acc[4][4][4];
#pragma unroll
    for (int a = 0; a < 4; a++)
#pragma unroll
        for (int b = 0; b < 4; b++)
#pragma unroll
            for (int c = 0; c < 4; c++) acc[a][b][c] = 0.0f;

    // per-lane ldmatrix address components
    const int a_radd = ((lane >> 3) & 1) * 8 + (lane & 7);   // m/n row add
    const int a_kadd = ((lane >> 4) & 1) * 8;                // k add (A)
    const int b_nadd = ((lane >> 4) & 1) * 8 + (lane & 7);   // n row add (B)
    const int b_kadd = ((lane >> 3) & 1) * 8;                // k add (B)

    gemm_stage(sb, 0, bm, bn, tid);
    gemm_stage(sb, 1, bm, bn, tid);
    gemm_stage(sb, 2, bm, bn, tid);

    for (int kc = 0; kc < 8; kc++) {
        asm volatile("cp.async.wait_group 2;");
        __syncthreads();
        uint32_t buf = sb + (uint32_t)(kc % 3) * G_BUFB;
#pragma unroll
        for (int s = 0; s < 4; s++) {
            uint32_t ah[4][4], al[4][4], bh[2][4], bl[2][4];
#pragma unroll
            for (int mt = 0; mt < 4; mt++) {
                uint32_t ra = buf +
                    (uint32_t)(wm * 64 + mt * 16 + a_radd) * (G_SAS * 2) +
                    (s * 16 + a_kadd) * 2;
                ldsm4(ah[mt], ra);
                ldsm4(al[mt], ra + G_MATB);
            }
#pragma unroll
            for (int nt16 = 0; nt16 < 2; nt16++) {
                uint32_t rb = buf + 2 * G_MATB +
                    (uint32_t)(wn * 32 + nt16 * 16 + b_nadd) * (G_SAS * 2) +
                    (s * 16 + b_kadd) * 2;
                ldsm4(bh[nt16], rb);
                ldsm4(bl[nt16], rb + G_MATB);
            }
#pragma unroll
            for (int mt = 0; mt < 4; mt++)
#pragma unroll
                for (int nt16 = 0; nt16 < 2; nt16++)
#pragma unroll
                    for (int hf = 0; hf < 2; hf++) {
                        int nt = nt16 * 2 + hf;
                        mma16816(acc[mt][nt], ah[mt], &bh[nt16][2 * hf]);
                        mma16816(acc[mt][nt], ah[mt], &bl[nt16][2 * hf]);
                        mma16816(acc[mt][nt], al[mt], &bh[nt16][2 * hf]);
                    }
        }
        __syncthreads();
        if (kc + 3 < 8) gemm_stage(sb, kc + 3, bm, bn, tid);
    }

    // epilogue: c frag (g=lane>>2, t=lane&3): rows g,g+8; cols 2t,2t+1
    const int g = lane >> 2, t2 = (lane & 3) * 2;
#pragma unroll
    for (int mt = 0; mt < 4; mt++)
#pragma unroll
        for (int nt = 0; nt < 4; nt++) {
            int row = bm + wm * 64 + mt * 16 + g;
            int col = bn + wn * 32 + nt * 8 + t2;
            float2 bv = *(const float2*)&bias[col];
            float2 v0 = make_float2(acc[mt][nt][0] + bv.x, acc[mt][nt][1] + bv.y);
            float2 v1 = make_float2(acc[mt][nt][2] + bv.x, acc[mt][nt][3] + bv.y);
            *(float2*)&g_XG[(size_t)row * NCOL + col] = v0;
            *(float2*)&g_XG[(size_t)(row + 8) * NCOL + col] = v1;
        }
}

// ---------------- grid barrier (sense-reversing, co-resident CTAs) -----------
__device__ __forceinline__ void grid_barrier(unsigned int s) {
    __threadfence();
    __syncthreads();
    if (threadIdx.x == 0) {
        unsigned int v = atomicAdd(&g_bar_count, 1u);
        if (v == gridDim.x - 1) {
            g_bar_count = 0u;
            __threadfence();
            g_bar_sense = s;
        } else {
            while (g_bar_sense != s) { }
            __threadfence();
        }
    }
    __syncthreads();
}

// ---------------- kernel 4: persistent recurrent LSTM via mma.sync -----------
// 64 CTAs x 256 thr. CTA owns 8 hidden units (32 gate-cols) x all 64 batches.
// Wh hi/lo slice resident in SMEM. H published as bf16 hi/lo in global,
// staged per step via cp.async (2 chunks). Warp tile m16 x n16, full K.
#define L_WROW 520                      // halves per W row (512 + 8)
#define L_HROW 264                      // halves per staged H row (256 + 8)
#define L_WB   (32 * L_WROW * 2)        // 33280 B per W split
#define L_HSPL (B_SZ * L_HROW * 2)      // 33792 B per H split per chunk buf
#define L_HBUF (2 * L_HSPL)             // 67584 B per chunk buffer (hi+lo)
#define L_HBASE (2 * L_WB)              // 66560
#define L_GSBASE (L_HBASE + 2 * L_HBUF) // 201728
#define L_SMEM (L_GSBASE + B_SZ * 34 * 4)  // 210432

__global__ void __launch_bounds__(256, 1)
lstm_mma(const float* __restrict__ h0, const float* __restrict__ c0,
         float* __restrict__ out) {
    extern __shared__ char sm[];
    const uint32_t sb = smem_u32(sm);
    float* Gs = (float*)(sm + L_GSBASE);    // [64][34] fp32

    const int tid = threadIdx.x;
    const int wid = tid >> 5;
    const int lane = tid & 31;
    const int wm = wid & 3;         // m-offset wm*16 (batch)
    const int wn = wid >> 2;        // n-offset wn*16 (gate-col)
    const int hu0 = blockIdx.x * 8; // first hidden unit of this CTA

    // ldmatrix per-lane address components
    const int a_radd = ((lane >> 3) & 1) * 8 + (lane & 7);
    const int a_kadd = ((lane >> 4) & 1) * 8;
    const int b_nadd = ((lane >> 4) & 1) * 8 + (lane & 7);
    const int b_kadd = ((lane >> 3) & 1) * 8;

    // Load W slice: row c (=g*8+j) -> global col (c>>3)*512 + hu0 + (c&7)
    // 32 rows x 64 segs x 2 splits = 4096 16B copies / 256 thr = 16 each
#pragma unroll
    for (int j = 0; j < 16; j++) {
        int lin = j * 256 + tid;
        int split = lin >> 11;
        int within = lin & 2047;
        int row = within >> 6;
        int seg = within & 63;
        size_t gcol = (size_t)((row >> 3) * HID_SZ + hu0 + (row & 7));
        const __nv_bfloat16* src =
            (split ? g_WHL : g_WHH) + gcol * HID_SZ + seg * 8;
        cpasync16(sb + (uint32_t)split * L_WB + row * (L_WROW * 2) + seg * 16, src);
    }
    cpasync_commit();

    // pointwise slots: slot s -> (b = s>>3, j = s&7); 2 slots per thread
    const int b0 = tid >> 3, j0 = tid & 7;
    const int b1 = (tid + 256) >> 3, j1 = tid & 7;

    float creg0 = c0[b0 * HID_SZ + hu0 + j0];
    float creg1 = c0[b1 * HID_SZ + hu0 + j1];

    // init H buffer 0 (bf16 hi/lo) for this CTA's units
    {
        float h_a = h0[b0 * HID_SZ + hu0 + j0];
        float h_b = h0[b1 * HID_SZ + hu0 + j1];
        split_bf16(h_a, g_HBH[0][b0 * HID_SZ + hu0 + j0],
                        g_HBL[0][b0 * HID_SZ + hu0 + j0]);
        split_bf16(h_b, g_HBH[0][b1 * HID_SZ + hu0 + j1],
                        g_HBL[0][b1 * HID_SZ + hu0 + j1]);
    }
    asm volatile("cp.async.wait_group 0;");
    grid_barrier(1);

    for (int t = 0; t < T_STEPS; t++) {
        const int cur = t & 1;

        // prefetch XG for pointwise
        const float* xga = &g_XG[(size_t)(t * B_SZ + b0) * NCOL + hu0 + j0];
        const float* xgb = &g_XG[(size_t)(t * B_SZ + b1) * NCOL + hu0 + j1];
        float xa0 = __ldg(xga + 0),    xb0 = __ldg(xgb + 0);
        float xa1 = __ldg(xga + 512),  xb1 = __ldg(xgb + 512);
        float xa2 = __ldg(xga + 1024), xb2 = __ldg(xgb + 1024);
        float xa3 = __ldg(xga + 1536), xb3 = __ldg(xgb + 1536);

        // stage both H chunks (hi+lo), one commit group per chunk
#pragma unroll
        for (int kc = 0; kc < 2; kc++) {
#pragma unroll
            for (int j = 0; j < 16; j++) {
                int lin = j * 256 + tid;           // 0..4095
                int split = lin >> 11;
                int within = lin & 2047;
                int row = within >> 5;             // batch 0..63
                int seg = within & 31;             // 16B seg within 256 halves
                const __nv_bfloat16* src =
                    (split ? g_HBL[cur] : g_HBH[cur]) +
                    (size_t)row * HID_SZ + kc * 256 + seg * 8;
                cpasync16(sb + L_HBASE + (uint32_t)kc * L_HBUF +
                          (uint32_t)split * L_HSPL + row * (L_HROW * 2) + seg * 16,
                          src);
            }
            cpasync_commit();
        }

        float acc[2][4];
#pragma unroll
        for (int n = 0; n < 2; n++)
#pragma unroll
            for (int c = 0; c < 4; c++) acc[n][c] = 0.0f;

#pragma unroll
        for (int kc = 0; kc < 2; kc++) {
            if (kc == 0) asm volatile("cp.async.wait_group 1;");
            else         asm volatile("cp.async.wait_group 0;");
            __syncthreads();
            uint32_t hb = sb + L_HBASE + (uint32_t)kc * L_HBUF;
#pragma unroll
            for (int s = 0; s < 16; s++) {
                uint32_t ah[4], al[4], bh[4], bl[4];
                uint32_t ra = hb + (uint32_t)(wm * 16 + a_radd) * (L_HROW * 2) +
                              (s * 16 + a_kadd) * 2;
                ldsm4(ah, ra);
                ldsm4(al, ra + L_HSPL);
                int kglob = kc * 256 + s * 16;
                uint32_t rb = sb + (uint32_t)(wn * 16 + b_nadd) * (L_WROW * 2) +
                              (kglob + b_kadd) * 2;
                ldsm4(bh, rb);
                ldsm4(bl, rb + L_WB);
#pragma unroll
                for (int hf = 0; hf < 2; hf++) {
                    mma16816(acc[hf], ah, &bh[2 * hf]);
                    mma16816(acc[hf], ah, &bl[2 * hf]);
                    mma16816(acc[hf], al, &bh[2 * hf]);
                }
            }
        }

        // store G frags -> Gs[64][34]
        {
            const int g = lane >> 2, t2 = (lane & 3) * 2;
#pragma unroll
            for (int nt = 0; nt < 2; nt++) {
                int row = wm * 16 + g;
                int col = wn * 16 + nt * 8 + t2;
                *(float2*)&Gs[row * 34 + col] =
                    make_float2(acc[nt][0], acc[nt][1]);
                *(float2*)&Gs[(row + 8) * 34 + col] =
                    make_float2(acc[nt][2], acc[nt][3]);
            }
        }
        __syncthreads();

        // pointwise LSTM cell, 2 slots per thread
        {
            float gi = Gs[b0 * 34 + 0  + j0] + xa0;
            float gf = Gs[b0 * 34 + 8  + j0] + xa1;
            float go = Gs[b0 * 34 + 16 + j0] + xa2;
            float gc = Gs[b0 * 34 + 24 + j0] + xa3;
            float I = 1.0f / (1.0f + expf(-gi));
            float F = 1.0f / (1.0f + expf(-gf));
            float O = 1.0f / (1.0f + expf(-go));
            float Ct = tanhf(gc);
            creg0 = F * creg0 + I * Ct;
            float h = O * tanhf(creg0);
            out[(size_t)(t * B_SZ + b0) * HID_SZ + hu0 + j0] = h;
            split_bf16(h, g_HBH[cur ^ 1][b0 * HID_SZ + hu0 + j0],
                          g_HBL[cur ^ 1][b0 * HID_SZ + hu0 + j0]);
        }
        {
            float gi = Gs[b1 * 34 + 0  + j1] + xb0;
            float gf = Gs[b1 * 34 + 8  + j1] + xb1;
            float go = Gs[b1 * 34 + 16 + j1] + xb2;
            float gc = Gs[b1 * 34 + 24 + j1] + xb3;
            float I = 1.0f / (1.0f + expf(-gi));
            float F = 1.0f / (1.0f + expf(-gf));
            float O = 1.0f / (1.0f + expf(-go));
            float Ct = tanhf(gc);
            creg1 = F * creg1 + I * Ct;
            float h = O * tanhf(creg1);
            out[(size_t)(t * B_SZ + b1) * HID_SZ + hu0 + j1] = h;
            split_bf16(h, g_HBH[cur ^ 1][b1 * HID_SZ + hu0 + j1],
                          g_HBL[cur ^ 1][b1 * HID_SZ + hu0 + j1]);
        }

        grid_barrier((unsigned)(t + 2));
    }
}

// ---------------- launcher ---------------------------------------------------
extern "C" void kernel_launch(void* const* d_in, const int* in_sizes, int n_in,
                              void* d_out, int out_size) {
    const float* X    = (const float*)d_in[0];   // (T,B,IN)
    const float* Wx   = (const float*)d_in[1];   // (4,HID,IN)
    const float* Wh   = (const float*)d_in[2];   // (4,HID,HID)
    const float* bias = (const float*)d_in[3];   // (4,HID)
    const float* thr  = (const float*)d_in[4];   // (HID,8)
    const float* h0   = (const float*)d_in[5];   // (B,HID)
    const float* c0   = (const float*)d_in[6];   // (B,HID)
    float* out = (float*)d_out;                  // (T,B,HID)

    // 1) masked weights -> bf16 hi/lo splits (Wx and Wh)
    mask_weights<<<(4 * HID_SZ * IN_SZ + 255) / 256, 256>>>(Wx, Wh, thr);

    // 2) X bf16 hi/lo splits
    split_x<<<(M_ROWS * IN_SZ / 4 + 255) / 256, 256>>>(X);

    // 3) input projection via mma.sync bf16 (3 products), triple-buffered
    const int gemm_smem = 3 * G_BUFB;   // 221184
    cudaFuncSetAttribute(gemm_mma,
                         cudaFuncAttributeMaxDynamicSharedMemorySize, gemm_smem);
    dim3 gg(NCOL / 128, M_ROWS / 128);  // (16, 512)
    gemm_mma<<<gg, 256, gemm_smem>>>(bias);

    // 4) persistent recurrent kernel (tensor cores)
    cudaFuncSetAttribute(lstm_mma,
                         cudaFuncAttributeMaxDynamicSharedMemorySize, L_SMEM);
    lstm_mma<<<64, 256, L_SMEM>>>(h0, c0, out);
}

// round 7
// speedup vs baseline: 2.1011x; 1.1873x over previous
#include <cuda_runtime.h>
#include <cuda_bf16.h>
#include <math.h>
#include <stdint.h>

// Problem constants
#define T_STEPS 1024
#define B_SZ    64
#define IN_SZ   512
#define HID_SZ  512
#define NCOL    2048               // 4 gates * HID
#define M_ROWS  (T_STEPS * B_SZ)   // 65536

// ---------------- device scratch (static; no runtime allocation) ------------
__device__ __nv_bfloat16 g_XH[(size_t)M_ROWS * IN_SZ];   // X hi split
__device__ __nv_bfloat16 g_XL[(size_t)M_ROWS * IN_SZ];   // X lo split
__device__ __nv_bfloat16 g_WXH[NCOL * IN_SZ];            // Wx hi [col][k]
__device__ __nv_bfloat16 g_WXL[NCOL * IN_SZ];            // Wx lo [col][k]
__device__ __nv_bfloat16 g_WHH[NCOL * HID_SZ];           // Wh hi [col][k]
__device__ __nv_bfloat16 g_WHL[NCOL * HID_SZ];           // Wh lo [col][k]
__device__ float g_XG[(size_t)M_ROWS * HID_SZ * 4];      // gate-interleaved [m][u][4]
__device__ __nv_bfloat16 g_HBH[2][B_SZ * HID_SZ];        // H hi [b][k], dbl buf
__device__ __nv_bfloat16 g_HBL[2][B_SZ * HID_SZ];        // H lo [b][k], dbl buf
__device__ unsigned int g_bar_count = 0;
__device__ volatile unsigned int g_bar_sense = 0;

// ---------------- helpers -----------------------------------------------------
__device__ __forceinline__ void split_bf16(float x, __nv_bfloat16& hi,
                                           __nv_bfloat16& lo) {
    hi = __float2bfloat16_rn(x);
    lo = __float2bfloat16_rn(x - __bfloat162float(hi));
}
__device__ __forceinline__ uint32_t smem_u32(const void* p) {
    uint32_t a;
    asm("{ .reg .u64 t; cvta.to.shared.u64 t, %1; cvt.u32.u64 %0, t; }"
        : "=r"(a) : "l"(p));
    return a;
}
__device__ __forceinline__ void cpasync16(uint32_t smem_dst, const void* gsrc) {
    asm volatile("cp.async.cg.shared.global [%0], [%1], 16;"
                 :: "r"(smem_dst), "l"(gsrc));
}
__device__ __forceinline__ void cpasync_commit() {
    asm volatile("cp.async.commit_group;");
}
__device__ __forceinline__ void ldsm4(uint32_t* r, uint32_t addr) {
    asm volatile("ldmatrix.sync.aligned.m8n8.x4.shared.b16 {%0,%1,%2,%3}, [%4];"
                 : "=r"(r[0]), "=r"(r[1]), "=r"(r[2]), "=r"(r[3]) : "r"(addr));
}
__device__ __forceinline__ void mma16816(float* c, const uint32_t* a,
                                         const uint32_t* b) {
    asm volatile(
        "mma.sync.aligned.m16n8k16.row.col.f32.bf16.bf16.f32 "
        "{%0,%1,%2,%3}, {%4,%5,%6,%7}, {%8,%9}, {%0,%1,%2,%3};"
        : "+f"(c[0]), "+f"(c[1]), "+f"(c[2]), "+f"(c[3])
        : "r"(a[0]), "r"(a[1]), "r"(a[2]), "r"(a[3]), "r"(b[0]), "r"(b[1]));
}
__device__ __forceinline__ float fsig(float x) {
    return 1.0f / (1.0f + __expf(-x));
}
__device__ __forceinline__ float ftanh(float x) {
    return 1.0f - 2.0f / (__expf(2.0f * x) + 1.0f);
}

// ---------------- kernel 1: threshold-mask + bf16 hi/lo weight splits --------
__global__ void mask_weights(const float* __restrict__ Wx,
                             const float* __restrict__ Wh,
                             const float* __restrict__ thr) {
    int idx = blockIdx.x * blockDim.x + threadIdx.x;   // over 4*512*512
    if (idx >= 4 * HID_SZ * IN_SZ) return;
    int g = idx / (HID_SZ * IN_SZ);
    int rem = idx % (HID_SZ * IN_SZ);
    int n = rem / IN_SZ;
    int i = rem % IN_SZ;
    size_t o = (size_t)(g * HID_SZ + n) * IN_SZ + i;

    float wx = Wx[idx];
    float vx = (fabsf(wx) >= thr[n * 8 + g]) ? wx : 0.0f;
    split_bf16(vx, g_WXH[o], g_WXL[o]);

    float wh = Wh[idx];
    float vh = (fabsf(wh) >= thr[n * 8 + 4 + g]) ? wh : 0.0f;
    split_bf16(vh, g_WHH[o], g_WHL[o]);
}

// ---------------- kernel 2: split X into bf16 hi/lo ---------------------------
__global__ void split_x(const float* __restrict__ X) {
    size_t i = ((size_t)blockIdx.x * blockDim.x + threadIdx.x) * 4;
    if (i >= (size_t)M_ROWS * IN_SZ) return;
    float4 x = *(const float4*)&X[i];
    __nv_bfloat16 h[4], l[4];
    split_bf16(x.x, h[0], l[0]);
    split_bf16(x.y, h[1], l[1]);
    split_bf16(x.z, h[2], l[2]);
    split_bf16(x.w, h[3], l[3]);
    *(__nv_bfloat162*)&g_XH[i]     = __nv_bfloat162(h[0], h[1]);
    *(__nv_bfloat162*)&g_XH[i + 2] = __nv_bfloat162(h[2], h[3]);
    *(__nv_bfloat162*)&g_XL[i]     = __nv_bfloat162(l[0], l[1]);
    *(__nv_bfloat162*)&g_XL[i + 2] = __nv_bfloat162(l[2], l[3]);
}

// ---------------- kernel 3: XG = X @ WX^T + bias via mma.sync bf16x2 ----------
// 128x128 tile, K chunks of 64, triple-buffered cp.async, 8 warps (2m x 4n).
// Epilogue writes gate-interleaved g_XG[m][u][gate].
#define G_SAS  72
#define G_MATB (128 * G_SAS * 2)
#define G_BUFB (4 * G_MATB)

__device__ __forceinline__ void gemm_stage(uint32_t sb, int kc, int bm, int bn,
                                           int tid) {
    uint32_t buf = sb + (uint32_t)(kc % 3) * G_BUFB;
#pragma unroll
    for (int j = 0; j < 16; j++) {
        int lin = j * 256 + tid;
        int mat = lin >> 10;
        int within = lin & 1023;
        int row = within >> 3;
        int seg = within & 7;
        uint32_t dst = buf + (uint32_t)mat * G_MATB + row * (G_SAS * 2) + seg * 16;
        size_t koff = (size_t)kc * 64 + seg * 8;
        const __nv_bfloat16* src;
        if (mat == 0)      src = &g_XH[(size_t)(bm + row) * IN_SZ + koff];
        else if (mat == 1) src = &g_XL[(size_t)(bm + row) * IN_SZ + koff];
        else if (mat == 2) src = &g_WXH[(size_t)(bn + row) * IN_SZ + koff];
        else               src = &g_WXL[(size_t)(bn + row) * IN_SZ + koff];
        cpasync16(dst, src);
    }
    cpasync_commit();
}

__global__ void __launch_bounds__(256, 1)
gemm_mma(const float* __restrict__ bias) {
    extern __shared__ char sm[];
    const uint32_t sb = smem_u32(sm);
    const int tid = threadIdx.x;
    const int wid = tid >> 5;
    const int lane = tid & 31;
    const int bm = blockIdx.y * 128;
    const int bn = blockIdx.x * 128;
    const int wm = wid & 1;
    const int wn = wid >> 1;

    float acc[4][4][4];
#pragma unroll
    for (int a = 0; a < 4; a++)
#pragma unroll
        for (int b = 0; b < 4; b++)
#pragma unroll
            for (int c = 0; c < 4; c++) acc[a][b][c] = 0.0f;

    const int a_radd = ((lane >> 3) & 1) * 8 + (lane & 7);
    const int a_kadd = ((lane >> 4) & 1) * 8;
    const int b_nadd = ((lane >> 4) & 1) * 8 + (lane & 7);
    const int b_kadd = ((lane >> 3) & 1) * 8;

    gemm_stage(sb, 0, bm, bn, tid);
    gemm_stage(sb, 1, bm, bn, tid);
    gemm_stage(sb, 2, bm, bn, tid);

    for (int kc = 0; kc < 8; kc++) {
        asm volatile("cp.async.wait_group 2;");
        __syncthreads();
        uint32_t buf = sb + (uint32_t)(kc % 3) * G_BUFB;
#pragma unroll
        for (int s = 0; s < 4; s++) {
            uint32_t ah[4][4], al[4][4], bh[2][4], bl[2][4];
#pragma unroll
            for (int mt = 0; mt < 4; mt++) {
                uint32_t ra = buf +
                    (uint32_t)(wm * 64 + mt * 16 + a_radd) * (G_SAS * 2) +
                    (s * 16 + a_kadd) * 2;
                ldsm4(ah[mt], ra);
                ldsm4(al[mt], ra + G_MATB);
            }
#pragma unroll
            for (int nt16 = 0; nt16 < 2; nt16++) {
                uint32_t rb = buf + 2 * G_MATB +
                    (uint32_t)(wn * 32 + nt16 * 16 + b_nadd) * (G_SAS * 2) +
                    (s * 16 + b_kadd) * 2;
                ldsm4(bh[nt16], rb);
                ldsm4(bl[nt16], rb + G_MATB);
            }
#pragma unroll
            for (int mt = 0; mt < 4; mt++)
#pragma unroll
                for (int nt16 = 0; nt16 < 2; nt16++)
#pragma unroll
                    for (int hf = 0; hf < 2; hf++) {
                        int nt = nt16 * 2 + hf;
                        mma16816(acc[mt][nt], ah[mt], &bh[nt16][2 * hf]);
                        mma16816(acc[mt][nt], ah[mt], &bl[nt16][2 * hf]);
                        mma16816(acc[mt][nt], al[mt], &bh[nt16][2 * hf]);
                    }
        }
        __syncthreads();
        if (kc + 3 < 8) gemm_stage(sb, kc + 3, bm, bn, tid);
    }

    // epilogue: gate-interleaved scatter, bias folded in
    const int g = lane >> 2, t2 = (lane & 3) * 2;
#pragma unroll
    for (int mt = 0; mt < 4; mt++)
#pragma unroll
        for (int nt = 0; nt < 4; nt++) {
            int row = bm + wm * 64 + mt * 16 + g;
            int col = bn + wn * 32 + nt * 8 + t2;
            int u = col & (HID_SZ - 1);
            int gate = col >> 9;
            float b0 = bias[col], b1 = bias[col + 1];
            g_XG[((size_t)row * HID_SZ + u) * 4 + gate]       = acc[mt][nt][0] + b0;
            g_XG[((size_t)row * HID_SZ + u + 1) * 4 + gate]   = acc[mt][nt][1] + b1;
            g_XG[((size_t)(row + 8) * HID_SZ + u) * 4 + gate] = acc[mt][nt][2] + b0;
            g_XG[((size_t)(row + 8) * HID_SZ + u + 1) * 4 + gate] = acc[mt][nt][3] + b1;
        }
}

// ---------------- grid barrier (sense-reversing, co-resident CTAs) -----------
__device__ __forceinline__ void grid_barrier(unsigned int s) {
    __threadfence();
    __syncthreads();
    if (threadIdx.x == 0) {
        unsigned int v = atomicAdd(&g_bar_count, 1u);
        if (v == gridDim.x - 1) {
            g_bar_count = 0u;
            __threadfence();
            g_bar_sense = s;
        } else {
            while (g_bar_sense != s) { }
            __threadfence();
        }
    }
    __syncthreads();
}

// ---------------- kernel 4: persistent recurrent LSTM via mma.sync -----------
// 128 CTAs = 64 col-groups x 2 batch-halves; CTA = 32 batches x 32 gate-cols.
// 8 warps = 2k x 2m x 2n (warp tile m16 n16, K=256 each). Each 64-thread
// (wk,wm) group stages exactly its own H block via its own cp.async group and
// syncs with a named barrier — no CTA-wide staging syncs. Wh hi/lo resident.
#define L_WROW 520
#define L_HROW 264
#define L_WB   (32 * L_WROW * 2)        // 33280 per W split
#define L_HSPL (32 * L_HROW * 2)        // 16896 per H split per chunk
#define L_HCH  (2 * L_HSPL)             // 33792 per k-chunk (hi+lo)
#define L_HBASE (2 * L_WB)              // 66560
#define L_GSBASE (L_HBASE + 2 * L_HCH)  // 134144
#define L_SMEM (L_GSBASE + 2 * 32 * 36 * 4)  // 143360

__global__ void __launch_bounds__(256, 1)
lstm_mma(const float* __restrict__ h0, const float* __restrict__ c0,
         float* __restrict__ out) {
    extern __shared__ char sm[];
    const uint32_t sb = smem_u32(sm);
    float* Gs0 = (float*)(sm + L_GSBASE);            // [32][36] partial k0
    float* Gs1 = Gs0 + 32 * 36;                      // [32][36] partial k1

    const int tid = threadIdx.x;
    const int wid = tid >> 5;
    const int lane = tid & 31;
    const int wk = wid & 1;         // k-half
    const int wm = (wid >> 1) & 1;  // m-tile (16 batches)
    const int wn = wid >> 2;        // n-tile (16 cols)
    const int grp = wid & 3;        // staging group (wk, wm)
    const int gl = wn * 32 + lane;  // lane within 64-thread group

    const int cg  = blockIdx.x >> 1;      // col group 0..63
    const int bh  = blockIdx.x & 1;       // batch half
    const int hu0 = cg * 8;

    const int a_radd = ((lane >> 3) & 1) * 8 + (lane & 7);
    const int a_kadd = ((lane >> 4) & 1) * 8;
    const int b_nadd = ((lane >> 4) & 1) * 8 + (lane & 7);
    const int b_kadd = ((lane >> 3) & 1) * 8;

    // Load resident W slice (32 rows x 512 k, hi+lo)
#pragma unroll
    for (int j = 0; j < 16; j++) {
        int lin = j * 256 + tid;
        int split = lin >> 11;
        int within = lin & 2047;
        int row = within >> 6;
        int seg = within & 63;
        size_t gcol = (size_t)((row >> 3) * HID_SZ + hu0 + (row & 7));
        const __nv_bfloat16* src =
            (split ? g_WHL : g_WHH) + gcol * HID_SZ + seg * 8;
        cpasync16(sb + (uint32_t)split * L_WB + row * (L_WROW * 2) + seg * 16, src);
    }
    cpasync_commit();

    // pointwise slot: (local batch pb, unit pj)
    const int pb = tid >> 3;
    const int pj = tid & 7;
    const int bg = bh * 32 + pb;

    float creg = c0[bg * HID_SZ + hu0 + pj];

    // init H buffer 0
    {
        float h = h0[bg * HID_SZ + hu0 + pj];
        split_bf16(h, g_HBH[0][bg * HID_SZ + hu0 + pj],
                      g_HBL[0][bg * HID_SZ + hu0 + pj]);
    }
    asm volatile("cp.async.wait_group 0;");
    grid_barrier(1);

    const float4* XG4 = (const float4*)g_XG;

    for (int t = 0; t < T_STEPS; t++) {
        const int cur = t & 1;

        // prefetch XG (1 LDG.128)
        float4 xg = __ldg(&XG4[(size_t)(t * B_SZ + bg) * HID_SZ + hu0 + pj]);

        // group (wk,wm) stages its own H block: rows [wm*16,+16), k [wk*256,+256)
#pragma unroll
        for (int j = 0; j < 16; j++) {
            int lin = j * 64 + gl;          // 0..1023
            int split = lin >> 9;
            int w = lin & 511;
            int r16 = w >> 5;               // 0..15
            int seg = w & 31;
            int row = wm * 16 + r16;
            int b = bh * 32 + row;
            const __nv_bfloat16* src =
                (split ? g_HBL[cur] : g_HBH[cur]) +
                (size_t)b * HID_SZ + wk * 256 + seg * 8;
            cpasync16(sb + L_HBASE + (uint32_t)wk * L_HCH +
                      (uint32_t)split * L_HSPL + row * (L_HROW * 2) + seg * 16,
                      src);
        }
        cpasync_commit();
        asm volatile("cp.async.wait_group 0;");
        asm volatile("bar.sync %0, 64;" :: "r"(grp + 1) : "memory");

        float acc[2][4];
#pragma unroll
        for (int n = 0; n < 2; n++)
#pragma unroll
            for (int c = 0; c < 4; c++) acc[n][c] = 0.0f;

        const uint32_t hb = sb + L_HBASE + (uint32_t)wk * L_HCH;
#pragma unroll
        for (int s = 0; s < 16; s++) {
            uint32_t ah[4], al[4], bhq[4], blq[4];
            uint32_t ra = hb + (uint32_t)(wm * 16 + a_radd) * (L_HROW * 2) +
                          (s * 16 + a_kadd) * 2;
            ldsm4(ah, ra);
            ldsm4(al, ra + L_HSPL);
            uint32_t rb = sb + (uint32_t)(wn * 16 + b_nadd) * (L_WROW * 2) +
                          (wk * 256 + s * 16 + b_kadd) * 2;
            ldsm4(bhq, rb);
            ldsm4(blq, rb + L_WB);
#pragma unroll
            for (int hf = 0; hf < 2; hf++) {
                mma16816(acc[hf], ah, &bhq[2 * hf]);
                mma16816(acc[hf], ah, &blq[2 * hf]);
                mma16816(acc[hf], al, &bhq[2 * hf]);
            }
        }

        // write partial G frags to this k-half's buffer
        {
            float* Gd = wk ? Gs1 : Gs0;
            const int g = lane >> 2, t2 = (lane & 3) * 2;
#pragma unroll
            for (int nt = 0; nt < 2; nt++) {
                int row = wm * 16 + g;
                int col = wn * 16 + nt * 8 + t2;
                *(float2*)&Gd[row * 36 + col] = make_float2(acc[nt][0], acc[nt][1]);
                *(float2*)&Gd[(row + 8) * 36 + col] = make_float2(acc[nt][2], acc[nt][3]);
            }
        }
        __syncthreads();

        // pointwise LSTM cell (1 slot per thread)
        {
            float gi = Gs0[pb * 36 + 0  + pj] + Gs1[pb * 36 + 0  + pj] + xg.x;
            float gf = Gs0[pb * 36 + 8  + pj] + Gs1[pb * 36 + 8  + pj] + xg.y;
            float go = Gs0[pb * 36 + 16 + pj] + Gs1[pb * 36 + 16 + pj] + xg.z;
            float gc = Gs0[pb * 36 + 24 + pj] + Gs1[pb * 36 + 24 + pj] + xg.w;
            float I = fsig(gi);
            float F = fsig(gf);
            float O = fsig(go);
            float Ct = ftanh(gc);
            creg = F * creg + I * Ct;
            float h = O * ftanh(creg);
            out[(size_t)(t * B_SZ + bg) * HID_SZ + hu0 + pj] = h;
            split_bf16(h, g_HBH[cur ^ 1][bg * HID_SZ + hu0 + pj],
                          g_HBL[cur ^ 1][bg * HID_SZ + hu0 + pj]);
        }

        grid_barrier((unsigned)(t + 2));
    }
}

// ---------------- launcher ---------------------------------------------------
extern "C" void kernel_launch(void* const* d_in, const int* in_sizes, int n_in,
                              void* d_out, int out_size) {
    const float* X    = (const float*)d_in[0];   // (T,B,IN)
    const float* Wx   = (const float*)d_in[1];   // (4,HID,IN)
    const float* Wh   = (const float*)d_in[2];   // (4,HID,HID)
    const float* bias = (const float*)d_in[3];   // (4,HID)
    const float* thr  = (const float*)d_in[4];   // (HID,8)
    const float* h0   = (const float*)d_in[5];   // (B,HID)
    const float* c0   = (const float*)d_in[6];   // (B,HID)
    float* out = (float*)d_out;                  // (T,B,HID)

    mask_weights<<<(4 * HID_SZ * IN_SZ + 255) / 256, 256>>>(Wx, Wh, thr);
    split_x<<<(M_ROWS * IN_SZ / 4 + 255) / 256, 256>>>(X);

    const int gemm_smem = 3 * G_BUFB;
    cudaFuncSetAttribute(gemm_mma,
                         cudaFuncAttributeMaxDynamicSharedMemorySize, gemm_smem);
    dim3 gg(NCOL / 128, M_ROWS / 128);
    gemm_mma<<<gg, 256, gemm_smem>>>(bias);

    cudaFuncSetAttribute(lstm_mma,
                         cudaFuncAttributeMaxDynamicSharedMemorySize, L_SMEM);
    lstm_mma<<<128, 256, L_SMEM>>>(h0, c0, out);
}